// round 15
// baseline (speedup 1.0000x reference)
#include <cuda_runtime.h>
#include <cuda_bf16.h>
#include <math.h>
#include <cstdint>

#define Bn 4
#define Sn 1024
#define Dn 1024
#define Hn 16
#define HDn 64
#define NEGV -10000000.0f

// ---------------- scratch (__device__ globals; no allocation allowed) ------
__device__ float QKVd[3][Bn * Hn * Sn * HDn];            // Q,K,V tf32-bit fp32
__device__ __nv_bfloat16 Xs1g[4096 * 1024];              // X hi plane [m][k]
__device__ __nv_bfloat16 Xs2g[4096 * 1024];              // X lo plane
__device__ __nv_bfloat16 Wt1g[3][1024 * 1024];           // W^T hi planes [mode][n][k]
__device__ __nv_bfloat16 Wt2g[3][1024 * 1024];           // W^T lo planes
__device__ unsigned adjbits_g[Bn * Sn * 32];             // mask bits, 1=masked

// ---------------- helpers ----------------
__device__ __forceinline__ unsigned f2tf(float x) {
    unsigned r; asm("cvt.rna.tf32.f32 %0, %1;" : "=r"(r) : "f"(x)); return r;
}
__device__ __forceinline__ uint32_t s2u(const void* p) {
    uint32_t a;
    asm("{ .reg .u64 t; cvta.to.shared.u64 t, %1; cvt.u32.u64 %0, t; }"
        : "=r"(a) : "l"(p));
    return a;
}
__device__ __forceinline__ void cpa16(uint32_t s, const void* g) {
    asm volatile("cp.async.cg.shared.global [%0], [%1], 16;" :: "r"(s), "l"(g));
}
#define CP_COMMIT() asm volatile("cp.async.commit_group;" ::: "memory")
#define CP_WAIT(n)  asm volatile("cp.async.wait_group %0;" :: "n"(n) : "memory")

__device__ __forceinline__ void ldsm4(unsigned r[4], uint32_t addr) {
    asm volatile("ldmatrix.sync.aligned.m8n8.x4.shared.b16 {%0,%1,%2,%3}, [%4];"
        : "=r"(r[0]), "=r"(r[1]), "=r"(r[2]), "=r"(r[3]) : "r"(addr));
}
__device__ __forceinline__ void mma8(float c[4], const unsigned a[4], const unsigned b[2]) {
    asm volatile(
        "mma.sync.aligned.m16n8k8.row.col.f32.tf32.tf32.f32 "
        "{%0,%1,%2,%3}, {%4,%5,%6,%7}, {%8,%9}, {%0,%1,%2,%3};\n"
        : "+f"(c[0]), "+f"(c[1]), "+f"(c[2]), "+f"(c[3])
        : "r"(a[0]), "r"(a[1]), "r"(a[2]), "r"(a[3]), "r"(b[0]), "r"(b[1]));
}
__device__ __forceinline__ void mma16(float c[4], const unsigned a[4], const unsigned b[2]) {
    asm volatile(
        "mma.sync.aligned.m16n8k16.row.col.f32.bf16.bf16.f32 "
        "{%0,%1,%2,%3}, {%4,%5,%6,%7}, {%8,%9}, {%0,%1,%2,%3};\n"
        : "+f"(c[0]), "+f"(c[1]), "+f"(c[2]), "+f"(c[3])
        : "r"(a[0]), "r"(a[1]), "r"(a[2]), "r"(a[3]), "r"(b[0]), "r"(b[1]));
}

// ---------------------------------------------------------------------------
// Prep kernels
// ---------------------------------------------------------------------------
__global__ __launch_bounds__(256)
void prep_x(const float* __restrict__ X) {
    const int i = blockIdx.x * blockDim.x + threadIdx.x;  // < 1048576
    float4 v = ((const float4*)X)[i];
    float vv[4] = {v.x, v.y, v.z, v.w};
    __nv_bfloat16 h[4], l[4];
#pragma unroll
    for (int j = 0; j < 4; j++) {
        h[j] = __float2bfloat16_rn(vv[j]);
        l[j] = __float2bfloat16_rn(vv[j] - __bfloat162float(h[j]));
    }
    ((__nv_bfloat162*)Xs1g)[2 * i] = __nv_bfloat162(h[0], h[1]);
    ((__nv_bfloat162*)Xs1g)[2 * i + 1] = __nv_bfloat162(h[2], h[3]);
    ((__nv_bfloat162*)Xs2g)[2 * i] = __nv_bfloat162(l[0], l[1]);
    ((__nv_bfloat162*)Xs2g)[2 * i + 1] = __nv_bfloat162(l[2], l[3]);
}

__global__ __launch_bounds__(256)
void prep_w(const float* __restrict__ Wq, const float* __restrict__ Wk,
            const float* __restrict__ Wv) {
    __shared__ float t[32][33];
    const int mode = blockIdx.z;
    const float* W = (mode == 0) ? Wq : (mode == 1) ? Wk : Wv;
    const int tx = threadIdx.x, ty = threadIdx.y;  // 32 x 8
    const int nb = blockIdx.x * 32, kb = blockIdx.y * 32;
#pragma unroll
    for (int j = 0; j < 4; j++) {
        const int k = kb + ty + j * 8;
        t[ty + j * 8][tx] = W[(size_t)k * 1024 + nb + tx];
    }
    __syncthreads();
#pragma unroll
    for (int j = 0; j < 4; j++) {
        const int n = nb + ty + j * 8;
        const int k = kb + tx;
        const float v = t[tx][ty + j * 8];
        __nv_bfloat16 h = __float2bfloat16_rn(v);
        Wt1g[mode][(size_t)n * 1024 + k] = h;
        Wt2g[mode][(size_t)n * 1024 + k] = __float2bfloat16_rn(v - __bfloat162float(h));
    }
}

// ---------------------------------------------------------------------------
// adj fused: passthrough copy to output AND bitmask build, single pass.
// ---------------------------------------------------------------------------
__global__ __launch_bounds__(256)
void adj_fused(const float4* __restrict__ src, float4* __restrict__ dst) {
    const int base = blockIdx.x * 1024 + threadIdx.x;
    const int lane = threadIdx.x & 31;
#pragma unroll
    for (int j = 0; j < 4; j++) {
        const int f = base + j * 256;   // float4 index; lanes consecutive
        float4 v = src[f];
        dst[f] = v;
        unsigned nib = (v.x < 0.5f ? 1u : 0u) | (v.y < 0.5f ? 2u : 0u)
                     | (v.z < 0.5f ? 4u : 0u) | (v.w < 0.5f ? 8u : 0u);
        unsigned word = nib << (4 * (lane & 7));
        word |= __shfl_xor_sync(0xffffffffu, word, 1);
        word |= __shfl_xor_sync(0xffffffffu, word, 2);
        word |= __shfl_xor_sync(0xffffffffu, word, 4);
        if ((lane & 7) == 0) adjbits_g[f >> 3] = word;
    }
}

// ---------------------------------------------------------------------------
// bf16x3 GEMM, fused over modes (grid.z). BM=128, BN=128, BK=32.
// 256 threads = 8 warps (4M x 2N), warp tile 32x64.
// cp.async double-buffer + ldmatrix; one barrier per mainloop iteration.
// ---------------------------------------------------------------------------
#define ASTR 40
#define PLANE (128 * ASTR)                 // bf16 per plane (A or B, 128 rows)
#define GBUF (4 * PLANE)                   // 20480 bf16 per buffer
#define GSMEM_BYTES (2 * GBUF * 2)         // 81920 B

__global__ __launch_bounds__(256, 2)
void gemm_bf3(const float* __restrict__ bq, const float* __restrict__ bk,
              const float* __restrict__ bv) {
    extern __shared__ __nv_bfloat16 sb[];
    const int tid = threadIdx.x;
    const int lane = tid & 31;
    const int wid = tid >> 5;
    const int g = lane >> 2;
    const int tg = lane & 3;
    const int mode = blockIdx.z;
    const int m0 = blockIdx.y * 128;
    const int n0 = blockIdx.x * 128;
    const int mw = (wid >> 1) * 32;      // warp m offset (4 warps)
    const int nw = (wid & 1) * 64;       // warp n offset (2 warps)
    const uint32_t sbase = s2u(sb);

    const __nv_bfloat16* W1 = Wt1g[mode];
    const __nv_bfloat16* W2 = Wt2g[mode];
    const float* bias = (mode == 0) ? bq : (mode == 1) ? bk : bv;

    float acc[2][8][4];
#pragma unroll
    for (int t = 0; t < 2; t++)
#pragma unroll
        for (int n = 0; n < 8; n++)
#pragma unroll
            for (int c = 0; c < 4; c++) acc[t][n][c] = 0.0f;

    auto stage = [&](int ki, int buf) {
        const uint32_t b0 = sbase + buf * (GBUF * 2);
        const int k0 = ki * 32;
#pragma unroll
        for (int e = tid; e < 512; e += 256) {
            const int r = e >> 2, c = e & 3;
            const uint32_t ds = (r * ASTR + c * 8) * 2;
            const size_t sa = (size_t)(m0 + r) * 1024 + k0 + c * 8;
            cpa16(b0 + ds, &Xs1g[sa]);
            cpa16(b0 + PLANE * 2 + ds, &Xs2g[sa]);
            const size_t sbm = (size_t)(n0 + r) * 1024 + k0 + c * 8;
            cpa16(b0 + 2 * PLANE * 2 + ds, &W1[sbm]);
            cpa16(b0 + 3 * PLANE * 2 + ds, &W2[sbm]);
        }
        CP_COMMIT();
    };

    const int lrow = lane & 7;
    const int lm8 = (lane >> 3) & 1;
    const int lkh = (lane >> 4) & 1;
    const int aRowOff = lrow + lm8 * 8;
    const int aKOff = lkh * 8;
    const int bRowOff = lrow + lkh * 8;
    const int bKOff = lm8 * 8;

    stage(0, 0);

    for (int i = 0; i < 32; i++) {
        CP_WAIT(0);
        __syncthreads();
        if (i < 31) stage(i + 1, (i + 1) & 1);

        const uint32_t b0 = sbase + (i & 1) * (GBUF * 2);
        const uint32_t A1 = b0;
        const uint32_t A2 = b0 + PLANE * 2;
        const uint32_t B1 = b0 + 2 * PLANE * 2;
        const uint32_t B2 = b0 + 3 * PLANE * 2;

#pragma unroll
        for (int ks = 0; ks < 2; ks++) {
            const int kk = ks * 16;
            unsigned ah[2][4], al[2][4], bh[4][4], bl[4][4];
#pragma unroll
            for (int t = 0; t < 2; t++) {
                const uint32_t ao = ((mw + t * 16 + aRowOff) * ASTR + kk + aKOff) * 2;
                ldsm4(ah[t], A1 + ao);
                ldsm4(al[t], A2 + ao);
            }
#pragma unroll
            for (int p = 0; p < 4; p++) {
                const uint32_t bo = ((nw + p * 16 + bRowOff) * ASTR + kk + bKOff) * 2;
                ldsm4(bh[p], B1 + bo);
                ldsm4(bl[p], B2 + bo);
            }
#pragma unroll
            for (int t = 0; t < 2; t++) {
#pragma unroll
                for (int n = 0; n < 8; n++) {
                    const unsigned* ph = &bh[n >> 1][(n & 1) * 2];
                    const unsigned* pl = &bl[n >> 1][(n & 1) * 2];
                    mma16(acc[t][n], ah[t], ph);
                    mma16(acc[t][n], ah[t], pl);
                    mma16(acc[t][n], al[t], ph);
                }
            }
        }
    }

    float* Out = QKVd[mode];
#pragma unroll
    for (int t = 0; t < 2; t++) {
#pragma unroll
        for (int n = 0; n < 8; n++) {
            const int col = n0 + nw + n * 8 + 2 * tg;
            const int hh = col >> 6, hd = col & 63;
            const float b0v = bias[col], b1v = bias[col + 1];
            const int r0 = m0 + mw + t * 16 + g;
            const int r1 = r0 + 8;
            const int ba0 = r0 >> 10, s0 = r0 & 1023;
            const int ba1 = r1 >> 10, s1 = r1 & 1023;
            float* d0 = Out + ((size_t)((ba0 * Hn + hh) * Sn + s0)) * HDn + hd;
            float* d1 = Out + ((size_t)((ba1 * Hn + hh) * Sn + s1)) * HDn + hd;
            *(float2*)d0 = make_float2(
                __uint_as_float(f2tf(acc[t][n][0] + b0v)),
                __uint_as_float(f2tf(acc[t][n][1] + b1v)));
            *(float2*)d1 = make_float2(
                __uint_as_float(f2tf(acc[t][n][2] + b0v)),
                __uint_as_float(f2tf(acc[t][n][3] + b1v)));
        }
    }
}

// ---------------------------------------------------------------------------
// Flash attention, no-max softmax. 128 threads = 4 warps x 16 q rows.
// ---------------------------------------------------------------------------
#define AST 68
#define C_SC_L2E 0.18033688011112042f   /* 0.125 * log2(e) */
#define C_MSK_L2E -14426950.408889634f  /* -1e7 * log2(e)  */

__global__ __launch_bounds__(128, 3)
void attn4(float* __restrict__ out) {
    extern __shared__ unsigned smu[];
    unsigned (*Qs)[AST] = (unsigned(*)[AST])smu;
    unsigned (*Ks)[AST] = (unsigned(*)[AST])(smu + 64 * AST);
    unsigned (*Vs)[AST] = (unsigned(*)[AST])(smu + 2 * 64 * AST);
    unsigned (*St)[AST] = (unsigned(*)[AST])(smu + 3 * 64 * AST);

    const int bh = blockIdx.x;
    const int q0 = blockIdx.y * 64;
    const int b = bh >> 4;
    const int hh = bh & 15;
    const int tid = threadIdx.x;
    const int wid = tid >> 5;
    const int lane = tid & 31;
    const int g = lane >> 2;
    const int tg = lane & 3;
    const int mw = wid * 16;

    const float* Qg = QKVd[0] + ((size_t)bh * Sn + q0) * HDn;
    const float* Kbase = QKVd[1] + (size_t)bh * Sn * HDn;
    const float* Vbase = QKVd[2] + (size_t)bh * Sn * HDn;
    const unsigned* mbase = adjbits_g + ((size_t)b * Sn) * 32;

    const uint32_t uKs = s2u(&Ks[0][0]);
    const uint32_t uVs = s2u(&Vs[0][0]);

    for (int e = tid; e < 64 * 16; e += 128) {
        const int q = e >> 4, c = (e & 15) * 4;
        *(uint4*)&Qs[q][c] = *(const uint4*)&Qg[(size_t)q * HDn + c];
    }

    float sum0 = 0.0f, sum1 = 0.0f;
    float oacc[8][4];
#pragma unroll
    for (int n = 0; n < 8; n++)
#pragma unroll
        for (int c = 0; c < 4; c++) oacc[n][c] = 0.0f;

    for (int kt = 0; kt < 16; kt++) {
        const int k0 = kt * 64;
        __syncthreads();
#pragma unroll
        for (int e = tid; e < 64 * 16; e += 128) {
            const int k = e >> 4, c = (e & 15) * 4;
            const uint32_t ds = (k * AST + c) * 4;
            cpa16(uKs + ds, &Kbase[(size_t)(k0 + k) * HDn + c]);
            cpa16(uVs + ds, &Vbase[(size_t)(k0 + k) * HDn + c]);
        }
        CP_COMMIT();
        CP_WAIT(0);
        __syncthreads();

        float sc[8][4];
#pragma unroll
        for (int n = 0; n < 8; n++)
#pragma unroll
            for (int c = 0; c < 4; c++) sc[n][c] = 0.0f;
#pragma unroll
        for (int kb = 0; kb < 64; kb += 8) {
            unsigned a[4];
            a[0] = Qs[mw + g][kb + tg];
            a[1] = Qs[mw + g + 8][kb + tg];
            a[2] = Qs[mw + g][kb + tg + 4];
            a[3] = Qs[mw + g + 8][kb + tg + 4];
#pragma unroll
            for (int n = 0; n < 8; n++) {
                unsigned bb[2] = {Ks[n * 8 + g][kb + tg], Ks[n * 8 + g][kb + tg + 4]};
                mma8(sc[n], a, bb);
            }
        }

        const uint2 wA = *(const uint2*)&mbase[(q0 + mw + g) * 32 + 2 * kt];
        const uint2 wB = *(const uint2*)&mbase[(q0 + mw + g + 8) * 32 + 2 * kt];
#pragma unroll
        for (int n = 0; n < 8; n++) {
            const int c0 = n * 8 + 2 * tg, c1 = c0 + 1;
            const unsigned bA0 = (c0 < 32 ? wA.x >> c0 : wA.y >> (c0 - 32)) & 1u;
            const unsigned bA1 = (c1 < 32 ? wA.x >> c1 : wA.y >> (c1 - 32)) & 1u;
            const unsigned bB0 = (c0 < 32 ? wB.x >> c0 : wB.y >> (c0 - 32)) & 1u;
            const unsigned bB1 = (c1 < 32 ? wB.x >> c1 : wB.y >> (c1 - 32)) & 1u;
            const float p0 = exp2f(fmaf(sc[n][0], C_SC_L2E, bA0 ? C_MSK_L2E : 0.0f));
            const float p1 = exp2f(fmaf(sc[n][1], C_SC_L2E, bA1 ? C_MSK_L2E : 0.0f));
            const float p2 = exp2f(fmaf(sc[n][2], C_SC_L2E, bB0 ? C_MSK_L2E : 0.0f));
            const float p3 = exp2f(fmaf(sc[n][3], C_SC_L2E, bB1 ? C_MSK_L2E : 0.0f));
            sum0 += p0 + p1;
            sum1 += p2 + p3;
            *(uint2*)&St[mw + g][c0] = make_uint2(f2tf(p0), f2tf(p1));
            *(uint2*)&St[mw + g + 8][c0] = make_uint2(f2tf(p2), f2tf(p3));
        }
        __syncwarp();

#pragma unroll
        for (int kb = 0; kb < 64; kb += 8) {
            unsigned a[4];
            a[0] = St[mw + g][kb + tg];
            a[1] = St[mw + g + 8][kb + tg];
            a[2] = St[mw + g][kb + tg + 4];
            a[3] = St[mw + g + 8][kb + tg + 4];
#pragma unroll
            for (int n = 0; n < 8; n++) {
                unsigned bb[2] = {Vs[kb + tg][n * 8 + g], Vs[kb + tg + 4][n * 8 + g]};
                mma8(oacc[n], a, bb);
            }
        }
    }

    sum0 += __shfl_xor_sync(0xffffffffu, sum0, 1);
    sum0 += __shfl_xor_sync(0xffffffffu, sum0, 2);
    sum1 += __shfl_xor_sync(0xffffffffu, sum1, 1);
    sum1 += __shfl_xor_sync(0xffffffffu, sum1, 2);
    const float inv0 = 1.0f / sum0, inv1 = 1.0f / sum1;
    const int r0 = q0 + mw + g, r1 = r0 + 8;
#pragma unroll
    for (int n = 0; n < 8; n++) {
        const int col = hh * HDn + n * 8 + 2 * tg;
        float* d0 = out + ((size_t)(b * Sn + r0)) * Dn + col;
        float* d1 = out + ((size_t)(b * Sn + r1)) * Dn + col;
        *(float2*)d0 = make_float2(fmaxf(oacc[n][0] * inv0, 0.0f),
                                   fmaxf(oacc[n][1] * inv0, 0.0f));
        *(float2*)d1 = make_float2(fmaxf(oacc[n][2] * inv1, 0.0f),
                                   fmaxf(oacc[n][3] * inv1, 0.0f));
    }
}

// ---------------------------------------------------------------------------
extern "C" void kernel_launch(void* const* d_in, const int* in_sizes, int n_in,
                              void* d_out, int out_size) {
    const float* x   = (const float*)d_in[0];
    const float* adj = (const float*)d_in[1];
    const float* Wq  = (const float*)d_in[2];
    const float* bq  = (const float*)d_in[3];
    const float* Wk  = (const float*)d_in[4];
    const float* bk  = (const float*)d_in[5];
    const float* Wv  = (const float*)d_in[6];
    const float* bv  = (const float*)d_in[7];
    float* out = (float*)d_out;

    static cudaStream_t s_side = nullptr;
    static cudaEvent_t ev_fork = nullptr, ev_w = nullptr, ev_join = nullptr;
    if (s_side == nullptr) {
        cudaStreamCreateWithFlags(&s_side, cudaStreamNonBlocking);
        cudaEventCreateWithFlags(&ev_fork, cudaEventDisableTiming);
        cudaEventCreateWithFlags(&ev_w, cudaEventDisableTiming);
        cudaEventCreateWithFlags(&ev_join, cudaEventDisableTiming);
    }

    cudaFuncSetAttribute(gemm_bf3, cudaFuncAttributeMaxDynamicSharedMemorySize,
                         GSMEM_BYTES);
    const int smem_attn = 4 * 64 * AST * (int)sizeof(unsigned);  // 69632
    cudaFuncSetAttribute(attn4, cudaFuncAttributeMaxDynamicSharedMemorySize, smem_attn);

    const int n_h = Bn * Sn * Dn;

    // ---- fork: side stream runs prep_w (needed by gemm) then adj work
    cudaEventRecord(ev_fork, 0);
    cudaStreamWaitEvent(s_side, ev_fork, 0);
    prep_w<<<dim3(32, 32, 3), dim3(32, 8), 0, s_side>>>(Wq, Wk, Wv);
    cudaEventRecord(ev_w, s_side);
    adj_fused<<<1024, 256, 0, s_side>>>((const float4*)adj, (float4*)(out + n_h));
    cudaEventRecord(ev_join, s_side);

    // ---- main chain: prep_x || prep_w, then fused GEMM
    prep_x<<<4096, 256>>>(x);
    cudaStreamWaitEvent(0, ev_w, 0);

    dim3 gg(Dn / 128, (Bn * Sn) / 128, 3);  // (8, 32, 3)
    gemm_bf3<<<gg, 256, GSMEM_BYTES>>>(bq, bk, bv);

    // ---- join: attention needs adjbits from the side branch
    cudaStreamWaitEvent(0, ev_join, 0);
    attn4<<<dim3(Bn * Hn, Sn / 64), 128, smem_attn>>>(out);
}

// round 16
// speedup vs baseline: 1.6030x; 1.6030x over previous
#include <cuda_runtime.h>
#include <cuda_fp16.h>
#include <math.h>
#include <cstdint>

#define Bn 4
#define Sn 1024
#define Dn 1024
#define Hn 16
#define HDn 64

// ---------------- scratch (__device__ globals; no allocation allowed) ------
// Q,K: fp16 [bh][s][hd].  V: fp16 [bh][hd][s] (transposed for PV mma).
__device__ __half QKVh[3][Bn * Hn * Sn * HDn];
__device__ __half Xh1g[4096 * 1024];             // X hi plane [m][k]
__device__ __half Xh2g[4096 * 1024];             // X lo plane
__device__ __half Wh1g[3][1024 * 1024];          // W^T fp16 [mode][n][k]
__device__ unsigned adjbits_g[Bn * Sn * 32];     // mask bits, 1=masked

// ---------------- helpers ----------------
__device__ __forceinline__ uint32_t s2u(const void* p) {
    uint32_t a;
    asm("{ .reg .u64 t; cvta.to.shared.u64 t, %1; cvt.u32.u64 %0, t; }"
        : "=r"(a) : "l"(p));
    return a;
}
__device__ __forceinline__ void cpa16(uint32_t s, const void* g) {
    asm volatile("cp.async.cg.shared.global [%0], [%1], 16;" :: "r"(s), "l"(g));
}
#define CP_COMMIT() asm volatile("cp.async.commit_group;" ::: "memory")
#define CP_WAIT(n)  asm volatile("cp.async.wait_group %0;" :: "n"(n) : "memory")

__device__ __forceinline__ void ldsm4(unsigned r[4], uint32_t addr) {
    asm volatile("ldmatrix.sync.aligned.m8n8.x4.shared.b16 {%0,%1,%2,%3}, [%4];"
        : "=r"(r[0]), "=r"(r[1]), "=r"(r[2]), "=r"(r[3]) : "r"(addr));
}
__device__ __forceinline__ void mma16h(float c[4], const unsigned a[4], const unsigned b[2]) {
    asm volatile(
        "mma.sync.aligned.m16n8k16.row.col.f32.f16.f16.f32 "
        "{%0,%1,%2,%3}, {%4,%5,%6,%7}, {%8,%9}, {%0,%1,%2,%3};\n"
        : "+f"(c[0]), "+f"(c[1]), "+f"(c[2]), "+f"(c[3])
        : "r"(a[0]), "r"(a[1]), "r"(a[2]), "r"(a[3]), "r"(b[0]), "r"(b[1]));
}

// ---------------------------------------------------------------------------
// Prep kernels
// ---------------------------------------------------------------------------
__global__ __launch_bounds__(256)
void prep_x(const float* __restrict__ X) {
    const int i = blockIdx.x * blockDim.x + threadIdx.x;  // float4 index
    float4 v = ((const float4*)X)[i];
    float vv[4] = {v.x, v.y, v.z, v.w};
    __half h[4], l[4];
#pragma unroll
    for (int j = 0; j < 4; j++) {
        h[j] = __float2half_rn(vv[j]);
        l[j] = __float2half_rn(vv[j] - __half2float(h[j]));
    }
    ((__half2*)Xh1g)[2 * i] = __half2(h[0], h[1]);
    ((__half2*)Xh1g)[2 * i + 1] = __half2(h[2], h[3]);
    ((__half2*)Xh2g)[2 * i] = __half2(l[0], l[1]);
    ((__half2*)Xh2g)[2 * i + 1] = __half2(l[2], l[3]);
}

__global__ __launch_bounds__(256)
void prep_w(const float* __restrict__ Wq, const float* __restrict__ Wk,
            const float* __restrict__ Wv) {
    __shared__ float t[32][33];
    const int mode = blockIdx.z;
    const float* W = (mode == 0) ? Wq : (mode == 1) ? Wk : Wv;
    const int tx = threadIdx.x, ty = threadIdx.y;  // 32 x 8
    const int nb = blockIdx.x * 32, kb = blockIdx.y * 32;
#pragma unroll
    for (int j = 0; j < 4; j++) {
        const int k = kb + ty + j * 8;
        t[ty + j * 8][tx] = W[(size_t)k * 1024 + nb + tx];
    }
    __syncthreads();
#pragma unroll
    for (int j = 0; j < 4; j++) {
        const int n = nb + ty + j * 8;
        const int k = kb + tx;
        Wh1g[mode][(size_t)n * 1024 + k] = __float2half_rn(t[tx][ty + j * 8]);
    }
}

// ---------------------------------------------------------------------------
// adj fused: passthrough copy + bitmask build, single pass.
// ---------------------------------------------------------------------------
__global__ __launch_bounds__(256)
void adj_fused(const float4* __restrict__ src, float4* __restrict__ dst) {
    const int base = blockIdx.x * 1024 + threadIdx.x;
    const int lane = threadIdx.x & 31;
#pragma unroll
    for (int j = 0; j < 4; j++) {
        const int f = base + j * 256;
        float4 v = src[f];
        dst[f] = v;
        unsigned nib = (v.x < 0.5f ? 1u : 0u) | (v.y < 0.5f ? 2u : 0u)
                     | (v.z < 0.5f ? 4u : 0u) | (v.w < 0.5f ? 8u : 0u);
        unsigned word = nib << (4 * (lane & 7));
        word |= __shfl_xor_sync(0xffffffffu, word, 1);
        word |= __shfl_xor_sync(0xffffffffu, word, 2);
        word |= __shfl_xor_sync(0xffffffffu, word, 4);
        if ((lane & 7) == 0) adjbits_g[f >> 3] = word;
    }
}

// ---------------------------------------------------------------------------
// fp16x2 GEMM, fused over modes (grid.z). BM=128, BN=64, BK=32.
// 256 threads = 8 warps (4M x 2N), warp tile 32x32.
// C = (Xhi + Xlo) @ W_fp16 : 2 mma passes per tile step.
// ---------------------------------------------------------------------------
#define ASTR 40
#define PLANE_A (128 * ASTR)                    // halves
#define PLANE_B (64 * ASTR)
#define GBUF (2 * PLANE_A + PLANE_B)            // 12800 halves = 25600 B
#define GSMEM_BYTES (2 * GBUF * 2)              // 51200 B

__global__ __launch_bounds__(256, 3)
void gemm_h2(const float* __restrict__ bq, const float* __restrict__ bk,
             const float* __restrict__ bv) {
    extern __shared__ __half sb[];
    const int tid = threadIdx.x;
    const int lane = tid & 31;
    const int wid = tid >> 5;
    const int g = lane >> 2;
    const int tg = lane & 3;
    const int mode = blockIdx.z;
    const int m0 = blockIdx.y * 128;
    const int n0 = blockIdx.x * 64;
    const int mw = (wid >> 1) * 32;
    const int nw = (wid & 1) * 32;
    const uint32_t sbase = s2u(sb);

    const __half* W1 = Wh1g[mode];
    const float* bias = (mode == 0) ? bq : (mode == 1) ? bk : bv;

    float acc[2][4][4];
#pragma unroll
    for (int t = 0; t < 2; t++)
#pragma unroll
        for (int n = 0; n < 4; n++)
#pragma unroll
            for (int c = 0; c < 4; c++) acc[t][n][c] = 0.0f;

    auto stage = [&](int ki, int buf) {
        const uint32_t b0 = sbase + buf * (GBUF * 2);
        const int k0 = ki * 32;
#pragma unroll
        for (int e = tid; e < 512; e += 256) {
            const int r = e >> 2, c = e & 3;
            const size_t src = (size_t)(m0 + r) * 1024 + k0 + c * 8;
            const uint32_t ds = (r * ASTR + c * 8) * 2;
            cpa16(b0 + ds, &Xh1g[src]);
            cpa16(b0 + PLANE_A * 2 + ds, &Xh2g[src]);
        }
        {
            const int e = tid & 255;
            const int r = e >> 2, c = e & 3;
            const size_t src = (size_t)(n0 + r) * 1024 + k0 + c * 8;
            cpa16(b0 + 2 * PLANE_A * 2 + (r * ASTR + c * 8) * 2, &W1[src]);
        }
        CP_COMMIT();
    };

    const int lrow = lane & 7;
    const int lm8 = (lane >> 3) & 1;
    const int lkh = (lane >> 4) & 1;
    const int aRowOff = lrow + lm8 * 8;
    const int aKOff = lkh * 8;
    const int bRowOff = lrow + lkh * 8;
    const int bKOff = lm8 * 8;

    stage(0, 0);

    for (int i = 0; i < 32; i++) {
        CP_WAIT(0);
        __syncthreads();
        if (i < 31) stage(i + 1, (i + 1) & 1);

        const uint32_t b0 = sbase + (i & 1) * (GBUF * 2);
        const uint32_t A1 = b0;
        const uint32_t A2 = b0 + PLANE_A * 2;
        const uint32_t B1 = b0 + 2 * PLANE_A * 2;

#pragma unroll
        for (int ks = 0; ks < 2; ks++) {
            const int kk = ks * 16;
            unsigned ah[2][4], al[2][4], bh01[4], bh23[4];
#pragma unroll
            for (int t = 0; t < 2; t++) {
                const uint32_t ao = ((mw + t * 16 + aRowOff) * ASTR + kk + aKOff) * 2;
                ldsm4(ah[t], A1 + ao);
                ldsm4(al[t], A2 + ao);
            }
            {
                const uint32_t bo0 = ((nw + bRowOff) * ASTR + kk + bKOff) * 2;
                const uint32_t bo1 = ((nw + 16 + bRowOff) * ASTR + kk + bKOff) * 2;
                ldsm4(bh01, B1 + bo0);
                ldsm4(bh23, B1 + bo1);
            }
#pragma unroll
            for (int t = 0; t < 2; t++) {
#pragma unroll
                for (int n = 0; n < 4; n++) {
                    const unsigned* ph = (n < 2) ? &bh01[(n & 1) * 2] : &bh23[(n & 1) * 2];
                    mma16h(acc[t][n], ah[t], ph);
                    mma16h(acc[t][n], al[t], ph);
                }
            }
        }
    }

    const int b = m0 >> 10, s0 = m0 & 1023;
    const int hh = n0 >> 6;
    if (mode < 2) {
        // Q, K: [bh][s][hd], fp16, direct pair stores
        __half* Out = QKVh[mode];
#pragma unroll
        for (int t = 0; t < 2; t++) {
#pragma unroll
            for (int n = 0; n < 4; n++) {
                const int col = n0 + nw + n * 8 + 2 * tg;
                const int hd = col & 63;
                const float b0v = bias[col], b1v = bias[col + 1];
                const int r0 = mw + t * 16 + g;
                const int r1 = r0 + 8;
                __half* d0 = Out + ((size_t)((b * Hn + hh) * Sn + s0 + r0)) * HDn + hd;
                __half* d1 = Out + ((size_t)((b * Hn + hh) * Sn + s0 + r1)) * HDn + hd;
                *(__half2*)d0 = __floats2half2_rn(acc[t][n][0] + b0v, acc[t][n][1] + b1v);
                *(__half2*)d1 = __floats2half2_rn(acc[t][n][2] + b0v, acc[t][n][3] + b1v);
            }
        }
    } else {
        // V: transpose through smem -> [bh][hd][s]
        __syncthreads();  // done with staging buffers
        __half* T = sb;   // [64 d][136 s-stride]
#pragma unroll
        for (int t = 0; t < 2; t++) {
#pragma unroll
            for (int n = 0; n < 4; n++) {
                const int col = nw + n * 8 + 2 * tg;        // local d
                const int gcol = n0 + col;
                const float b0v = bias[gcol], b1v = bias[gcol + 1];
                const int r0 = mw + t * 16 + g;
                const int r1 = r0 + 8;
                T[(col + 0) * 136 + r0] = __float2half_rn(acc[t][n][0] + b0v);
                T[(col + 1) * 136 + r0] = __float2half_rn(acc[t][n][1] + b1v);
                T[(col + 0) * 136 + r1] = __float2half_rn(acc[t][n][2] + b0v);
                T[(col + 1) * 136 + r1] = __float2half_rn(acc[t][n][3] + b1v);
            }
        }
        __syncthreads();
        __half* Out = QKVh[2];
        // 64 d rows x 128 halves, coalesced uint4 stores
        for (int e = tid; e < 64 * 16; e += 256) {
            const int d = e >> 4, c = (e & 15) * 8;
            *(uint4*)&Out[((size_t)((b * Hn + hh) * HDn + d)) * Sn + s0 + c] =
                *(const uint4*)&T[d * 136 + c];
        }
    }
}

// ---------------------------------------------------------------------------
// Flash attention, fp16 mma16, no-max softmax. 128 threads = 4 warps.
// smem word layout: Qs/Ks/Vt/St each 64 rows x 36 words (72 halves).
// ---------------------------------------------------------------------------
#define AW 36   // words per row
#define C_SC_L2E 0.18033688011112042f   /* 0.125 * log2(e) */
#define C_MSK_L2E -14426950.408889634f  /* -1e7 * log2(e)  */

__global__ __launch_bounds__(128, 4)
void attn5(float* __restrict__ out) {
    extern __shared__ unsigned smu[];
    const uint32_t sbase = s2u(smu);
    unsigned* Qs = smu;                 // [64][36] words
    unsigned* Ks = smu + 64 * AW;
    unsigned* Vt = smu + 2 * 64 * AW;
    unsigned* St = smu + 3 * 64 * AW;
    const uint32_t uQs = sbase;
    const uint32_t uKs = sbase + 64 * AW * 4;
    const uint32_t uVt = sbase + 2 * 64 * AW * 4;

    const int bh = blockIdx.x;
    const int q0 = blockIdx.y * 64;
    const int b = bh >> 4;
    const int hh = bh & 15;
    const int tid = threadIdx.x;
    const int wid = tid >> 5;
    const int lane = tid & 31;
    const int g = lane >> 2;
    const int tg = lane & 3;
    const int mw = wid * 16;

    const __half* Qg = QKVh[0] + ((size_t)bh * Sn + q0) * HDn;
    const __half* Kbase = QKVh[1] + (size_t)bh * Sn * HDn;
    const __half* Vtb = QKVh[2] + (size_t)bh * HDn * Sn;   // [hd][s]
    const unsigned* mbase = adjbits_g + ((size_t)b * Sn) * 32;

    // stage Q (64 tokens x 64 halves) via cp.async; commits with first tile
    for (int e = tid; e < 64 * 8; e += 128) {
        const int r = e >> 3, c = e & 7;
        cpa16(uQs + r * 144 + c * 16, &Qg[(size_t)r * HDn + c * 8]);
    }

    float sum0 = 0.0f, sum1 = 0.0f;
    float oacc[8][4];
#pragma unroll
    for (int n = 0; n < 8; n++)
#pragma unroll
        for (int c = 0; c < 4; c++) oacc[n][c] = 0.0f;

    for (int kt = 0; kt < 16; kt++) {
        const int k0 = kt * 64;
        __syncthreads();   // prior tile's readers done with Ks/Vt
#pragma unroll
        for (int e = tid; e < 64 * 8; e += 128) {
            const int r = e >> 3, c = e & 7;
            cpa16(uKs + r * 144 + c * 16, &Kbase[(size_t)(k0 + r) * HDn + c * 8]);
            cpa16(uVt + r * 144 + c * 16, &Vtb[(size_t)r * Sn + k0 + c * 8]);
        }
        CP_COMMIT();
        CP_WAIT(0);
        __syncthreads();

        // ---- QK^T : 4 k-steps of 16 ----
        float sc[8][4];
#pragma unroll
        for (int n = 0; n < 8; n++)
#pragma unroll
            for (int c = 0; c < 4; c++) sc[n][c] = 0.0f;
#pragma unroll
        for (int ksp = 0; ksp < 4; ksp++) {
            const int kb2 = ksp * 8;
            unsigned a[4];
            a[0] = Qs[(mw + g) * AW + kb2 + tg];
            a[1] = Qs[(mw + g + 8) * AW + kb2 + tg];
            a[2] = Qs[(mw + g) * AW + kb2 + tg + 4];
            a[3] = Qs[(mw + g + 8) * AW + kb2 + tg + 4];
#pragma unroll
            for (int n = 0; n < 8; n++) {
                unsigned bb[2] = {Ks[(n * 8 + g) * AW + kb2 + tg],
                                  Ks[(n * 8 + g) * AW + kb2 + tg + 4]};
                mma16h(sc[n], a, bb);
            }
        }

        // ---- mask + exp (no max subtraction) ----
        const uint2 wA = *(const uint2*)&mbase[(q0 + mw + g) * 32 + 2 * kt];
        const uint2 wB = *(const uint2*)&mbase[(q0 + mw + g + 8) * 32 + 2 * kt];
#pragma unroll
        for (int n = 0; n < 8; n++) {
            const int c0 = n * 8 + 2 * tg, c1 = c0 + 1;
            const unsigned bA0 = (c0 < 32 ? wA.x >> c0 : wA.y >> (c0 - 32)) & 1u;
            const unsigned bA1 = (c1 < 32 ? wA.x >> c1 : wA.y >> (c1 - 32)) & 1u;
            const unsigned bB0 = (c0 < 32 ? wB.x >> c0 : wB.y >> (c0 - 32)) & 1u;
            const unsigned bB1 = (c1 < 32 ? wB.x >> c1 : wB.y >> (c1 - 32)) & 1u;
            const float p0 = exp2f(fmaf(sc[n][0], C_SC_L2E, bA0 ? C_MSK_L2E : 0.0f));
            const float p1 = exp2f(fmaf(sc[n][1], C_SC_L2E, bA1 ? C_MSK_L2E : 0.0f));
            const float p2 = exp2f(fmaf(sc[n][2], C_SC_L2E, bB0 ? C_MSK_L2E : 0.0f));
            const float p3 = exp2f(fmaf(sc[n][3], C_SC_L2E, bB1 ? C_MSK_L2E : 0.0f));
            sum0 += p0 + p1;
            sum1 += p2 + p3;
            __half2 h01 = __floats2half2_rn(p0, p1);
            __half2 h23 = __floats2half2_rn(p2, p3);
            St[(mw + g) * AW + 4 * n + tg] = *(unsigned*)&h01;
            St[(mw + g + 8) * AW + 4 * n + tg] = *(unsigned*)&h23;
        }
        __syncwarp();

        // ---- P @ V : 4 k-steps of 16 ----
#pragma unroll
        for (int ksp = 0; ksp < 4; ksp++) {
            const int kb2 = ksp * 8;
            unsigned a[4];
            a[0] = St[(mw + g) * AW + kb2 + tg];
            a[1] = St[(mw + g + 8) * AW + kb2 + tg];
            a[2] = St[(mw + g) * AW + kb2 + tg + 4];
            a[3] = St[(mw + g + 8) * AW + kb2 + tg + 4];
#pragma unroll
            for (int n = 0; n < 8; n++) {
                unsigned bb[2] = {Vt[(n * 8 + g) * AW + kb2 + tg],
                                  Vt[(n * 8 + g) * AW + kb2 + tg + 4]};
                mma16h(oacc[n], a, bb);
            }
        }
    }

    sum0 += __shfl_xor_sync(0xffffffffu, sum0, 1);
    sum0 += __shfl_xor_sync(0xffffffffu, sum0, 2);
    sum1 += __shfl_xor_sync(0xffffffffu, sum1, 1);
    sum1 += __shfl_xor_sync(0xffffffffu, sum1, 2);
    const float inv0 = 1.0f / sum0, inv1 = 1.0f / sum1;
    const int r0 = q0 + mw + g, r1 = r0 + 8;
#pragma unroll
    for (int n = 0; n < 8; n++) {
        const int col = hh * HDn + n * 8 + 2 * tg;
        float* d0 = out + ((size_t)(b * Sn + r0)) * Dn + col;
        float* d1 = out + ((size_t)(b * Sn + r1)) * Dn + col;
        *(float2*)d0 = make_float2(fmaxf(oacc[n][0] * inv0, 0.0f),
                                   fmaxf(oacc[n][1] * inv0, 0.0f));
        *(float2*)d1 = make_float2(fmaxf(oacc[n][2] * inv1, 0.0f),
                                   fmaxf(oacc[n][3] * inv1, 0.0f));
    }
}

// ---------------------------------------------------------------------------
extern "C" void kernel_launch(void* const* d_in, const int* in_sizes, int n_in,
                              void* d_out, int out_size) {
    const float* x   = (const float*)d_in[0];
    const float* adj = (const float*)d_in[1];
    const float* Wq  = (const float*)d_in[2];
    const float* bq  = (const float*)d_in[3];
    const float* Wk  = (const float*)d_in[4];
    const float* bk  = (const float*)d_in[5];
    const float* Wv  = (const float*)d_in[6];
    const float* bv  = (const float*)d_in[7];
    float* out = (float*)d_out;

    static cudaStream_t s_side = nullptr;
    static cudaEvent_t ev_fork = nullptr, ev_w = nullptr, ev_join = nullptr;
    if (s_side == nullptr) {
        cudaStreamCreateWithFlags(&s_side, cudaStreamNonBlocking);
        cudaEventCreateWithFlags(&ev_fork, cudaEventDisableTiming);
        cudaEventCreateWithFlags(&ev_w, cudaEventDisableTiming);
        cudaEventCreateWithFlags(&ev_join, cudaEventDisableTiming);
    }

    cudaFuncSetAttribute(gemm_h2, cudaFuncAttributeMaxDynamicSharedMemorySize,
                         GSMEM_BYTES);
    const int smem_attn = 4 * 64 * AW * 4;  // 36864 B
    cudaFuncSetAttribute(attn5, cudaFuncAttributeMaxDynamicSharedMemorySize, smem_attn);

    const int n_h = Bn * Sn * Dn;

    // ---- fork: side stream runs prep_w (needed by gemm) then adj work
    cudaEventRecord(ev_fork, 0);
    cudaStreamWaitEvent(s_side, ev_fork, 0);
    prep_w<<<dim3(32, 32, 3), dim3(32, 8), 0, s_side>>>(Wq, Wk, Wv);
    cudaEventRecord(ev_w, s_side);
    adj_fused<<<1024, 256, 0, s_side>>>((const float4*)adj, (float4*)(out + n_h));
    cudaEventRecord(ev_join, s_side);

    // ---- main chain: prep_x || prep_w, then fused GEMM
    prep_x<<<4096, 256>>>(x);
    cudaStreamWaitEvent(0, ev_w, 0);

    dim3 gg(Dn / 64, (Bn * Sn) / 128, 3);  // (16, 32, 3)
    gemm_h2<<<gg, 256, GSMEM_BYTES>>>(bq, bk, bv);

    // ---- join: attention needs adjbits from the side branch
    cudaStreamWaitEvent(0, ev_join, 0);
    attn5<<<dim3(Bn * Hn, Sn / 64), 128, smem_attn>>>(out);
}